// round 4
// baseline (speedup 1.0000x reference)
#include <cuda_runtime.h>
#include <math.h>
#include <float.h>

#define NPTS 16384
#define HDIM 256
#define HD2  128
#define TR   8          // rows per block in emb kernel
#define TILE_C 1024     // candidates per smem tile in topk kernel
#define TOPK_THREADS 64

typedef unsigned long long u64;

// ---------------- static device scratch (no allocations allowed) ------------
__device__ u64   g_xp[NPTS / 2];   // packed (x[2i], x[2i+1])
__device__ u64   g_yp[NPTS / 2];   // packed (y[2i], y[2i+1])
__device__ u64   g_sp[NPTS / 2];   // packed (s[2i], s[2i+1]), s = x^2+y^2
__device__ float g_mean[NPTS];     // mean of 6 NN distances per row

// ---------------- f32x2 packed helpers (sm_100+ PTX) ------------------------
__device__ __forceinline__ void ffma2(u64 &acc, u64 a, u64 b) {
    asm("fma.rn.f32x2 %0, %1, %2, %0;" : "+l"(acc) : "l"(a), "l"(b));
}
__device__ __forceinline__ u64 pack2(float x, float y) {
    u64 r; asm("mov.b64 %0, {%1, %2};" : "=l"(r) : "f"(x), "f"(y)); return r;
}
__device__ __forceinline__ void unpack2(u64 v, float &lo, float &hi) {
    asm("mov.b64 {%0, %1}, %2;" : "=f"(lo), "=f"(hi) : "l"(v));
}

// ---------------- kernel 0: pack candidate table (SoA, pairs) ---------------
__global__ void prep_kernel(const float* __restrict__ coords) {
    int i = blockIdx.x * blockDim.x + threadIdx.x;   // pair index
    if (i < NPTS / 2) {
        float4 c = ((const float4*)coords)[i];       // (x0,y0,x1,y1)
        float s0 = fmaf(c.x, c.x, c.y * c.y);
        float s1 = fmaf(c.z, c.z, c.w * c.w);
        g_xp[i] = pack2(c.x, c.z);
        g_yp[i] = pack2(c.y, c.w);
        g_sp[i] = pack2(s0, s1);
    }
}

// ---------------- kernel 1: full-scan 7-NN + mean of 6 NN dists -------------
__device__ __forceinline__ void insert7(float d, float t[7], float &worst) {
    bool done = false;
    #pragma unroll
    for (int i = 0; i < 7; i++) {
        if (!done && t[i] == worst) { t[i] = d; done = true; }
    }
    float w = t[0];
    #pragma unroll
    for (int i = 1; i < 7; i++) w = fmaxf(w, t[i]);
    worst = w;
}

__global__ void __launch_bounds__(TOPK_THREADS) topk_kernel(
    const float* __restrict__ coords)
{
    __shared__ __align__(16) u64 sx[TILE_C / 2];   // 4 KB
    __shared__ __align__(16) u64 sy[TILE_C / 2];   // 4 KB
    __shared__ __align__(16) u64 ss[TILE_C / 2];   // 4 KB

    int row = blockIdx.x * TOPK_THREADS + threadIdx.x;
    float2 me = ((const float2*)coords)[row];
    float a0 = -2.0f * me.x;
    float a1 = -2.0f * me.y;
    float si = fmaf(me.x, me.x, me.y * me.y);
    u64 A0 = pack2(a0, a0);
    u64 A1 = pack2(a1, a1);

    float t[7];
    #pragma unroll
    for (int i = 0; i < 7; i++) t[i] = FLT_MAX;
    float worst = FLT_MAX;

    for (int tb = 0; tb < NPTS / 2; tb += TILE_C / 2) {
        // exact trip count (8) so ptxas fully unrolls & front-batches the LDGs
        #pragma unroll
        for (int u = 0; u < (TILE_C / 2) / TOPK_THREADS; u++) {
            int i = u * TOPK_THREADS + threadIdx.x;
            sx[i] = g_xp[tb + i];
            sy[i] = g_yp[tb + i];
            ss[i] = g_sp[tb + i];
        }
        __syncthreads();

        // 4 candidates (2 packed pairs) per step; shifted d2 = a0*x + a1*y + s
        #pragma unroll 4
        for (int c = 0; c < TILE_C / 2; c += 2) {
            u64 d01 = ss[c];
            u64 d23 = ss[c + 1];
            ffma2(d01, A1, sy[c]);
            ffma2(d23, A1, sy[c + 1]);
            ffma2(d01, A0, sx[c]);
            ffma2(d23, A0, sx[c + 1]);
            float e0, e1, e2, e3;
            unpack2(d01, e0, e1);
            unpack2(d23, e2, e3);
            float m = fminf(fminf(e0, e1), fminf(e2, e3));
            if (m < worst) {
                if (e0 < worst) insert7(e0, t, worst);
                if (e1 < worst) insert7(e1, t, worst);
                if (e2 < worst) insert7(e2, t, worst);
                if (e3 < worst) insert7(e3, t, worst);
            }
        }
        __syncthreads();
    }

    // t[] = 7 smallest shifted-d2 (self = -si is the strict minimum).
    // dist = sqrt(max(shifted + si, 1e-12)); mean over the 6 non-self values.
    float sum = 0.0f, mn = FLT_MAX;
    #pragma unroll
    for (int i = 0; i < 7; i++) {
        float dist = sqrtf(fmaxf(t[i] + si, 1e-12f));
        sum += dist;
        mn = fminf(mn, dist);
    }
    g_mean[row] = (sum - mn) * (1.0f / 6.0f);
}

// -------- kernel 2: out = silu(x@W1+b1)@W2+b2 + silu(m@Wd1+bd1)@Wd2+bd2 -----
__global__ void __launch_bounds__(HDIM) emb_kernel(
    const float* __restrict__ coords,
    const float* __restrict__ W1,  const float* __restrict__ b1,
    const float* __restrict__ W2,  const float* __restrict__ b2,
    const float* __restrict__ Wd1, const float* __restrict__ bd1,
    const float* __restrict__ Wd2, const float* __restrict__ bd2,
    float* __restrict__ out)
{
    __shared__ __align__(16) float h1s[HDIM][TR];   // 8 KB, [k][r]
    __shared__ __align__(16) float us[HD2][TR];     // 4 KB, [k][r]
    __shared__ float2 xs[TR];
    __shared__ float  ms[TR];

    int j  = threadIdx.x;          // output column / hidden index
    int r0 = blockIdx.x * TR;      // first row of this block

    if (j < TR) {
        xs[j] = ((const float2*)coords)[r0 + j];
        ms[j] = g_mean[r0 + j];
    }
    __syncthreads();

    // hidden activations for the coord MLP (all 256 lanes)
    {
        float w1a = W1[j];
        float w1b = W1[HDIM + j];
        float bb  = b1[j];
        #pragma unroll
        for (int r = 0; r < TR; r++) {
            float h = fmaf(xs[r].x, w1a, fmaf(xs[r].y, w1b, bb));
            float sg = 1.0f / (1.0f + __expf(-h));
            h1s[j][r] = h * sg;
        }
    }
    // hidden activations for the dist MLP (first 128 lanes)
    if (j < HD2) {
        float w = Wd1[j];
        float b = bd1[j];
        #pragma unroll
        for (int r = 0; r < TR; r++) {
            float h = fmaf(ms[r], w, b);
            float sg = 1.0f / (1.0f + __expf(-h));
            us[j][r] = h * sg;
        }
    }
    __syncthreads();

    // out[r][j] = sum_k h1[r][k]*W2[k][j] + sum_k u[r][k]*Wd2[k][j] + b2[j] + bd2[j]
    u64 acc0 = 0ull, acc1 = 0ull, acc2 = 0ull, acc3 = 0ull;
    #pragma unroll 4
    for (int k = 0; k < HDIM; k++) {
        float w  = W2[k * HDIM + j];
        u64  ww  = pack2(w, w);
        const u64* hp = (const u64*)&h1s[k][0];
        ffma2(acc0, hp[0], ww);
        ffma2(acc1, hp[1], ww);
        ffma2(acc2, hp[2], ww);
        ffma2(acc3, hp[3], ww);
    }
    #pragma unroll 4
    for (int k = 0; k < HD2; k++) {
        float w  = Wd2[k * HDIM + j];
        u64  ww  = pack2(w, w);
        const u64* hp = (const u64*)&us[k][0];
        ffma2(acc0, hp[0], ww);
        ffma2(acc1, hp[1], ww);
        ffma2(acc2, hp[2], ww);
        ffma2(acc3, hp[3], ww);
    }
    float bj = b2[j] + bd2[j];
    float lo, hi;
    unpack2(acc0, lo, hi);
    out[(r0 + 0) * HDIM + j] = lo + bj;  out[(r0 + 1) * HDIM + j] = hi + bj;
    unpack2(acc1, lo, hi);
    out[(r0 + 2) * HDIM + j] = lo + bj;  out[(r0 + 3) * HDIM + j] = hi + bj;
    unpack2(acc2, lo, hi);
    out[(r0 + 4) * HDIM + j] = lo + bj;  out[(r0 + 5) * HDIM + j] = hi + bj;
    unpack2(acc3, lo, hi);
    out[(r0 + 6) * HDIM + j] = lo + bj;  out[(r0 + 7) * HDIM + j] = hi + bj;
}

// ---------------- launch ----------------------------------------------------
extern "C" void kernel_launch(void* const* d_in, const int* in_sizes, int n_in,
                              void* d_out, int out_size)
{
    const float* coords = (const float*)d_in[0];
    const float* W1  = (const float*)d_in[1];
    const float* b1  = (const float*)d_in[2];
    const float* W2  = (const float*)d_in[3];
    const float* b2  = (const float*)d_in[4];
    const float* Wd1 = (const float*)d_in[5];
    const float* bd1 = (const float*)d_in[6];
    const float* Wd2 = (const float*)d_in[7];
    const float* bd2 = (const float*)d_in[8];
    float* out = (float*)d_out;

    prep_kernel<<<(NPTS / 2 + 255) / 256, 256>>>(coords);
    topk_kernel<<<NPTS / TOPK_THREADS, TOPK_THREADS>>>(coords);
    emb_kernel<<<NPTS / TR, HDIM>>>(coords, W1, b1, W2, b2,
                                    Wd1, bd1, Wd2, bd2, out);
}

// round 7
// speedup vs baseline: 1.1516x; 1.1516x over previous
#include <cuda_runtime.h>
#include <math.h>
#include <float.h>

#define NPTS 16384
#define HDIM 256
#define HD2  128
#define TR   32          // rows per block in emb kernel
#define TRP  36          // padded row stride (floats): 16B-aligned, 4-way STS conflicts only
#define TILE_C 1024      // candidates per smem tile in topk kernel
#define TOPK_BLOCK 256   // threads per topk block (64 rows x 4 quarters)
#define ROWS_PB 64

typedef unsigned long long u64;

// ---------------- static device scratch (no allocations allowed) ------------
__device__ __align__(16) u64 g_xp[NPTS / 2];   // packed (x[2i], x[2i+1])
__device__ __align__(16) u64 g_yp[NPTS / 2];   // packed (y[2i], y[2i+1])
__device__ __align__(16) u64 g_sp[NPTS / 2];   // packed (s[2i], s[2i+1]), s=x^2+y^2
__device__ float g_mean[NPTS];                 // mean of 6 NN distances per row

// ---------------- f32x2 packed helpers (sm_100+ PTX) ------------------------
__device__ __forceinline__ void ffma2(u64 &acc, u64 a, u64 b) {
    asm("fma.rn.f32x2 %0, %1, %2, %0;" : "+l"(acc) : "l"(a), "l"(b));
}
__device__ __forceinline__ u64 pack2(float x, float y) {
    u64 r; asm("mov.b64 %0, {%1, %2};" : "=l"(r) : "f"(x), "f"(y)); return r;
}
__device__ __forceinline__ void unpack2(u64 v, float &lo, float &hi) {
    asm("mov.b64 {%0, %1}, %2;" : "=f"(lo), "=f"(hi) : "l"(v));
}

// ---------------- kernel 0: pack candidate table (SoA, pairs) ---------------
__global__ void prep_kernel(const float* __restrict__ coords) {
    int i = blockIdx.x * blockDim.x + threadIdx.x;   // pair index
    if (i < NPTS / 2) {
        float4 c = ((const float4*)coords)[i];       // (x0,y0,x1,y1)
        float s0 = fmaf(c.x, c.x, c.y * c.y);
        float s1 = fmaf(c.z, c.z, c.w * c.w);
        g_xp[i] = pack2(c.x, c.z);
        g_yp[i] = pack2(c.y, c.w);
        g_sp[i] = pack2(s0, s1);
    }
}

// ---------------- kernel 1: 7-NN scan, 4 threads per row --------------------
__device__ __forceinline__ void insert7(float d, float t[7], float &worst) {
    bool done = false;
    #pragma unroll
    for (int i = 0; i < 7; i++) {
        if (!done && t[i] == worst) { t[i] = d; done = true; }
    }
    float w = t[0];
    #pragma unroll
    for (int i = 1; i < 7; i++) w = fmaxf(w, t[i]);
    worst = w;
}

__global__ void __launch_bounds__(TOPK_BLOCK) topk_kernel(
    const float* __restrict__ coords)
{
    __shared__ __align__(16) u64 sx[TILE_C / 2];       // 4 KB
    __shared__ __align__(16) u64 sy[TILE_C / 2];       // 4 KB
    __shared__ __align__(16) u64 ss[TILE_C / 2];       // 4 KB
    __shared__ float tcand[TOPK_BLOCK][7];             // 7 KB partial top-7 lists

    int tid       = threadIdx.x;
    int row_local = tid & (ROWS_PB - 1);
    int quarter   = tid >> 6;                          // warp-uniform
    int row       = blockIdx.x * ROWS_PB + row_local;

    float2 me = ((const float2*)coords)[row];
    float a0 = -2.0f * me.x;
    float a1 = -2.0f * me.y;
    float si = fmaf(me.x, me.x, me.y * me.y);
    u64 A0 = pack2(a0, a0);
    u64 A1 = pack2(a1, a1);

    float t[7];
    #pragma unroll
    for (int i = 0; i < 7; i++) t[i] = FLT_MAX;
    float worst = FLT_MAX;

    int base = quarter << 7;                           // u64 offset of this quarter

    for (int tile = 0; tile < NPTS / TILE_C; tile++) {
        int tb2 = tile * (TILE_C / 4);                 // ulonglong2 offset
        ((ulonglong2*)sx)[tid] = ((const ulonglong2*)g_xp)[tb2 + tid];
        ((ulonglong2*)sy)[tid] = ((const ulonglong2*)g_yp)[tb2 + tid];
        ((ulonglong2*)ss)[tid] = ((const ulonglong2*)g_sp)[tb2 + tid];
        __syncthreads();

        // 8 candidates (4 packed pairs) per iteration; shifted d2 = a0*x + a1*y + s
        #pragma unroll 2
        for (int c = 0; c < 128; c += 4) {
            ulonglong2 s01 = *(const ulonglong2*)&ss[base + c];
            ulonglong2 s23 = *(const ulonglong2*)&ss[base + c + 2];
            ulonglong2 y01 = *(const ulonglong2*)&sy[base + c];
            ulonglong2 y23 = *(const ulonglong2*)&sy[base + c + 2];
            ulonglong2 x01 = *(const ulonglong2*)&sx[base + c];
            ulonglong2 x23 = *(const ulonglong2*)&sx[base + c + 2];
            u64 d0 = s01.x, d1 = s01.y, d2 = s23.x, d3 = s23.y;
            ffma2(d0, A1, y01.x);  ffma2(d1, A1, y01.y);
            ffma2(d2, A1, y23.x);  ffma2(d3, A1, y23.y);
            ffma2(d0, A0, x01.x);  ffma2(d1, A0, x01.y);
            ffma2(d2, A0, x23.x);  ffma2(d3, A0, x23.y);
            float e0, e1, e2, e3, e4, e5, e6, e7;
            unpack2(d0, e0, e1);  unpack2(d1, e2, e3);
            unpack2(d2, e4, e5);  unpack2(d3, e6, e7);
            float m = fminf(fminf(fminf(e0, e1), fminf(e2, e3)),
                            fminf(fminf(e4, e5), fminf(e6, e7)));
            if (m < worst) {
                if (e0 < worst) insert7(e0, t, worst);
                if (e1 < worst) insert7(e1, t, worst);
                if (e2 < worst) insert7(e2, t, worst);
                if (e3 < worst) insert7(e3, t, worst);
                if (e4 < worst) insert7(e4, t, worst);
                if (e5 < worst) insert7(e5, t, worst);
                if (e6 < worst) insert7(e6, t, worst);
                if (e7 < worst) insert7(e7, t, worst);
            }
        }
        __syncthreads();
    }

    #pragma unroll
    for (int i = 0; i < 7; i++) tcand[tid][i] = t[i];
    __syncthreads();

    // quarter-0 threads merge the 4 partial lists (28 values -> 7 smallest),
    // drop the global min (self), mean of the 6 remaining sqrt'd distances.
    if (quarter == 0) {
        float v[28];
        #pragma unroll
        for (int q = 0; q < 4; q++)
            #pragma unroll
            for (int i = 0; i < 7; i++)
                v[q * 7 + i] = tcand[row_local + ROWS_PB * q][i];

        float sum = 0.0f;
        #pragma unroll
        for (int it = 0; it < 7; it++) {
            float m = v[0]; int mi = 0;
            #pragma unroll
            for (int i = 1; i < 28; i++)
                if (v[i] < m) { m = v[i]; mi = i; }
            v[mi] = FLT_MAX;
            if (it > 0)                       // it==0 is the self point
                sum += sqrtf(fmaxf(m + si, 1e-12f));
        }
        g_mean[row] = sum * (1.0f / 6.0f);
    }
}

// -------- kernel 2: out = silu(x@W1+b1)@W2+b2 + silu(m@Wd1+bd1)@Wd2+bd2 -----
__global__ void __launch_bounds__(HDIM) emb_kernel(
    const float* __restrict__ coords,
    const float* __restrict__ W1,  const float* __restrict__ b1,
    const float* __restrict__ W2,  const float* __restrict__ b2,
    const float* __restrict__ Wd1, const float* __restrict__ bd1,
    const float* __restrict__ Wd2, const float* __restrict__ bd2,
    float* __restrict__ out)
{
    __shared__ __align__(16) float h1s[HDIM][TRP];   // 36 KB, [k][r]
    __shared__ __align__(16) float us[HD2][TRP];     // 18 KB, [k][r]
    __shared__ float2 xs[TR];
    __shared__ float  ms[TR];

    int j  = threadIdx.x;          // output column / hidden index
    int r0 = blockIdx.x * TR;      // first row of this block

    if (j < TR) {
        xs[j] = ((const float2*)coords)[r0 + j];
        ms[j] = g_mean[r0 + j];
    }
    __syncthreads();

    // hidden activations for the coord MLP (all 256 lanes)
    {
        float w1a = W1[j];
        float w1b = W1[HDIM + j];
        float bb  = b1[j];
        #pragma unroll
        for (int r = 0; r < TR; r++) {
            float h = fmaf(xs[r].x, w1a, fmaf(xs[r].y, w1b, bb));
            float sg = 1.0f / (1.0f + __expf(-h));
            h1s[j][r] = h * sg;
        }
    }
    // hidden activations for the dist MLP (first 128 lanes)
    if (j < HD2) {
        float w = Wd1[j];
        float b = bd1[j];
        #pragma unroll
        for (int r = 0; r < TR; r++) {
            float h = fmaf(ms[r], w, b);
            float sg = 1.0f / (1.0f + __expf(-h));
            us[j][r] = h * sg;
        }
    }
    __syncthreads();

    // out[r][j] = sum_k h1[r][k]*W2[k][j] + sum_k u[r][k]*Wd2[k][j] + b2[j]+bd2[j]
    u64 acc[TR / 2];
    #pragma unroll
    for (int i = 0; i < TR / 2; i++) acc[i] = 0ull;

    #pragma unroll 2
    for (int k = 0; k < HDIM; k++) {
        float w  = W2[k * HDIM + j];
        u64  ww  = pack2(w, w);
        const u64* hp = (const u64*)&h1s[k][0];
        #pragma unroll
        for (int i = 0; i < TR / 2; i++) ffma2(acc[i], hp[i], ww);
    }
    #pragma unroll 2
    for (int k = 0; k < HD2; k++) {
        float w  = Wd2[k * HDIM + j];
        u64  ww  = pack2(w, w);
        const u64* hp = (const u64*)&us[k][0];
        #pragma unroll
        for (int i = 0; i < TR / 2; i++) ffma2(acc[i], hp[i], ww);
    }

    float bj = b2[j] + bd2[j];
    #pragma unroll
    for (int i = 0; i < TR / 2; i++) {
        float lo, hi;
        unpack2(acc[i], lo, hi);
        out[(r0 + 2 * i + 0) * HDIM + j] = lo + bj;
        out[(r0 + 2 * i + 1) * HDIM + j] = hi + bj;
    }
}

// ---------------- launch ----------------------------------------------------
extern "C" void kernel_launch(void* const* d_in, const int* in_sizes, int n_in,
                              void* d_out, int out_size)
{
    const float* coords = (const float*)d_in[0];
    const float* W1  = (const float*)d_in[1];
    const float* b1  = (const float*)d_in[2];
    const float* W2  = (const float*)d_in[3];
    const float* b2  = (const float*)d_in[4];
    const float* Wd1 = (const float*)d_in[5];
    const float* bd1 = (const float*)d_in[6];
    const float* Wd2 = (const float*)d_in[7];
    const float* bd2 = (const float*)d_in[8];
    float* out = (float*)d_out;

    prep_kernel<<<(NPTS / 2 + 255) / 256, 256>>>(coords);
    topk_kernel<<<NPTS / ROWS_PB, TOPK_BLOCK>>>(coords);
    emb_kernel<<<NPTS / TR, HDIM>>>(coords, W1, b1, W2, b2,
                                    Wd1, bd1, Wd2, bd2, out);
}